// round 1
// baseline (speedup 1.0000x reference)
#include <cuda_runtime.h>
#include <cstddef>

// CRF loss, B=512, N=1024, K=64.
// out[b] = logsumexp(alpha_final) - (point + trans_pairs)
// Forward recursion done in exp-domain: s_j = sum_i exp(alpha_i - R) * E_ij,
// E = exp(trans) held per-thread (column) in registers.
// One block per batch, 64 threads (one state per thread), one barrier/step,
// double-buffered shared a[], ref, mask flags, y_true chunks.

#define KK 64
#define NN 1024
#define BB 512
#define L2E 1.4426950408889634f
#define LN2 0.6931471805599453f

__device__ __forceinline__ float fast_ex2(float x) {
    float y; asm("ex2.approx.f32 %0, %1;" : "=f"(y) : "f"(x)); return y;
}
__device__ __forceinline__ float fast_lg2(float x) {
    float y; asm("lg2.approx.f32 %0, %1;" : "=f"(y) : "f"(x)); return y;
}

__global__ __launch_bounds__(KK) void crf_kernel(
    const float* __restrict__ y_pred,   // [B, N, K]
    const float* __restrict__ trans,    // [K, K]
    const int*   __restrict__ y_true,   // [B, N]
    float*       __restrict__ out)      // [B]
{
    const int b = blockIdx.x;
    const int j = threadIdx.x;

    __shared__ __align__(16) float aS[2][KK];
    __shared__ float refS[2];
    __shared__ int   flagS[2][2];
    __shared__ int   ytS[2][KK];
    __shared__ float red[KK];

    // E column: E[i] = exp(trans[i][j])
    float E[KK];
#pragma unroll
    for (int i = 0; i < KK; i++)
        E[i] = fast_ex2(trans[i * KK + j] * L2E);

    const float* yp = y_pred + (size_t)b * NN * KK + j;
    const int* yt_row = y_true + b * NN;

    // y_true chunk 0 into shared
    ytS[0][j] = yt_row[j];

    // ---- prologue: t = 0 ----
    float e_cur = yp[0];
    float e_n1  = yp[(size_t)1 * KK];
    float e_n2  = yp[(size_t)2 * KK];

    {
        bool ok = e_cur > -1000000.0f;
        unsigned bal = __ballot_sync(0xFFFFFFFFu, ok);
        if ((j & 31) == 0) flagS[0][j >> 5] = (bal == 0xFFFFFFFFu) ? 1 : 0;
    }
    __syncthreads();
    int m0 = flagS[0][0] & flagS[0][1];

    float alpha = m0 ? e_cur : 0.0f;
    float point = 0.0f, tsum = 0.0f;
    int yt_prev = ytS[0][0];
    if (m0 && j == yt_prev) point = e_cur;
    int m_prev = m0;
    float R = 0.0f;   // stale reference offset; exact value irrelevant, only range

    // shift emit pipeline: e_cur = emit[1], e_n1 = emit[2], e_n2 = emit[3]
    e_cur = e_n1; e_n1 = e_n2;
    e_n2 = yp[(size_t)3 * KK];

    int yt_pref = 0;

    // ---- main loop: t = 1 .. N-1 ----
    for (int t = 1; t < NN; ++t) {
        const int pb = t & 1;

        // Phase A (writes, pre-barrier)
        float aj = fast_ex2((alpha - R) * L2E);
        aS[pb][j] = aj;
        if (j == 0) refS[pb] = alpha;      // publish alpha_0 of step t-1 as next R

        bool okc = e_cur > -1000000.0f;
        unsigned bl = __ballot_sync(0xFFFFFFFFu, okc);
        if ((j & 31) == 0) flagS[pb][j >> 5] = (bl == 0xFFFFFFFFu) ? 1 : 0;

        // y_true chunk prefetch (LDG early in chunk, STS mid-chunk)
        if ((t & 63) == 1 && t < NN - 64) yt_pref = yt_row[(t & ~63) + 64 + j];
        if ((t & 63) == 48 && t < NN - 64) ytS[((t >> 6) + 1) & 1][j] = yt_pref;

        __syncthreads();

        // Phase B (reads, post-barrier)
        const int mm = flagS[pb][0] & flagS[pb][1];
        const float newR = refS[pb];

        const float4* a4 = (const float4*)aS[pb];
        float s0 = 0.0f, s1 = 0.0f, s2 = 0.0f, s3 = 0.0f;
#pragma unroll
        for (int q = 0; q < 16; q++) {
            float4 v = a4[q];
            s0 = fmaf(v.x, E[4 * q + 0], s0);
            s1 = fmaf(v.y, E[4 * q + 1], s1);
            s2 = fmaf(v.z, E[4 * q + 2], s2);
            s3 = fmaf(v.w, E[4 * q + 3], s3);
        }
        float s = (s0 + s1) + (s2 + s3);
        float na = R + LN2 * fast_lg2(s) + e_cur;

        const int yt = ytS[(t >> 6) & 1][t & 63];
        if (mm) {
            alpha = na;
            if (j == yt) point += e_cur;
        }
        // transition score for pair (t-1, t): one designated thread per step
        if (j == (t & 63) && (mm & m_prev)) tsum += __ldg(&trans[yt_prev * KK + yt]);

        R = newR;
        m_prev = mm;
        yt_prev = yt;

        // emit prefetch, distance 3
        e_cur = e_n1; e_n1 = e_n2;
        e_n2 = (t + 3 < NN) ? yp[(size_t)(t + 3) * KK] : 0.0f;
    }

    // ---- epilogue: log_norm = logsumexp(alpha), out = log_norm - point - tsum ----
    red[j] = alpha;
    __syncthreads();
    if (j < 32) {
        float v = fmaxf(red[j], red[j + 32]);
#pragma unroll
        for (int o = 16; o > 0; o >>= 1)
            v = fmaxf(v, __shfl_xor_sync(0xFFFFFFFFu, v, o));
        if (j == 0) refS[0] = v;
    }
    __syncthreads();
    const float mx = refS[0];
    red[j] = fast_ex2((alpha - mx) * L2E);
    __syncthreads();
    if (j < 32) {
        float v = red[j] + red[j + 32];
#pragma unroll
        for (int o = 16; o > 0; o >>= 1)
            v += __shfl_xor_sync(0xFFFFFFFFu, v, o);
        if (j == 0) refS[0] = mx + LN2 * fast_lg2(v);   // log_norm
    }
    __syncthreads();
    red[j] = point + tsum;
    __syncthreads();
    if (j < 32) {
        float v = red[j] + red[j + 32];
#pragma unroll
        for (int o = 16; o > 0; o >>= 1)
            v += __shfl_xor_sync(0xFFFFFFFFu, v, o);
        if (j == 0) out[b] = refS[0] - v;
    }
}

extern "C" void kernel_launch(void* const* d_in, const int* in_sizes, int n_in,
                              void* d_out, int out_size) {
    const float* y_pred = (const float*)d_in[0];
    const float* trans  = (const float*)d_in[1];
    const int*   y_true = (const int*)d_in[2];
    float* out = (float*)d_out;
    crf_kernel<<<BB, KK>>>(y_pred, trans, y_true, out);
}